// round 9
// baseline (speedup 1.0000x reference)
#include <cuda_runtime.h>
#include <cuda_fp16.h>

#define BB 256
#define TT 32

typedef unsigned long long ULL;

// Device-global scratch: Whh fp16, layout [m=16][r=512][8 halves]
__device__ __half g_WhhH[16 * 512 * 8];

__device__ __forceinline__ float fast_tanh(float x) {
    float y;
    asm("tanh.approx.f32 %0, %1;" : "=f"(y) : "f"(x));
    return y;
}
__device__ __forceinline__ float fast_sig(float x) {
    return 0.5f + 0.5f * fast_tanh(0.5f * x);
}
__device__ __forceinline__ ULL fma2(ULL a, ULL b, ULL c) {
    ULL d;
    asm("fma.rn.f32x2 %0, %1, %2, %3;" : "=l"(d) : "l"(a), "l"(b), "l"(c));
    return d;
}
__device__ __forceinline__ float2 unpack2(ULL v) {
    float2 r;
    asm("mov.b64 {%0, %1}, %2;" : "=f"(r.x), "=f"(r.y) : "l"(v));
    return r;
}
__device__ __forceinline__ ULL pack2(float a) {
    ULL v;
    asm("mov.b64 %0, {%1, %1};" : "=l"(v) : "f"(a));
    return v;
}
__device__ __forceinline__ ULL pack2f(float2 f) {
    ULL v;
    asm("mov.b64 %0, {%1, %2};" : "=l"(v) : "f"(f.x), "f"(f.y));
    return v;
}
__device__ __forceinline__ float2 h2tof2(unsigned u) {
    __half2 h = *reinterpret_cast<__half2*>(&u);
    return __half22float2(h);
}
__device__ __forceinline__ ULL h2f2(unsigned u) {
    return pack2f(h2tof2(u));
}

// fp32 master hc layout: quarters of 64 floats at stride 68; batch stride 272.
#define HQ 68
#define HB 272
// fp16 shadow hc layout: quarters of 64 halves at stride 72; batch stride 288.
#define HQH 72
#define HBH 288

// ---------------------------------------------------------------------------
__global__ void __launch_bounds__(128)
whh_prep(const float* __restrict__ Whh)   // [512,128]
{
    int base = blockIdx.x * 8192;
    for (int i = base + threadIdx.x; i < base + 8192; i += 128) {
        int j = i & 7;
        int r = (i >> 3) & 511;
        int m = i >> 12;
        g_WhhH[i] = __float2half(Whh[r * 128 + (m << 3) + j]);
    }
}

// ---------------------------------------------------------------------------
// Main: 128 blocks x 512 threads, 2 batches/block. 4 barriers per step.
// ---------------------------------------------------------------------------
__global__ void __launch_bounds__(512, 1)
decoder_kernel(const float* __restrict__ enc,     // [B,32,128]
               const float* __restrict__ yhist,   // [B,32]
               const float* __restrict__ W1,      // [128,384] cols [h|c|enc]
               const float* __restrict__ b1,      // [128]
               const float* __restrict__ W2,      // [128]
               const float* __restrict__ Wih,     // [512]
               const float* __restrict__ bih,     // [512]
               const float* __restrict__ bhh,     // [512]
               const float* __restrict__ fcW,     // [129]
               const float* __restrict__ fcb,     // [1]
               const float* __restrict__ fcfW,    // [256]
               const float* __restrict__ fcfb,    // [1]
               float* __restrict__ out)           // [256]
{
    extern __shared__ float sm[];
    float*  sWhh  = sm;                 // 32768 fl = 128KB fp16 Whh
    float*  sEnc  = sWhh + 32768;       // 8448 [64 rows][132] fp32
    __half* sE1h  = (__half*)(sEnc + 8448);  // 8192 halves = 4096 fl
    __half* sHh   = (__half*)(sEnc + 8448 + 4096); // 576 halves -> 292 fl
    float*  sHp   = sEnc + 8448 + 4096 + 292;      // 552 fp32 master hc
    float*  sgp   = sHp + 552;          // 2048 [kh][g][512] gate partials
    float*  su    = sgp + 2048;         // 256  [g][128]
    float*  sctxC = su + 256;           // 256  [g][128]
    float*  sWih  = sctxC + 256;        // 512
    float*  sbias = sWih + 512;         // 512
    float*  sW2   = sbias + 512;        // 128
    float*  sfcf  = sW2 + 128;          // 256
    float*  sfc   = sfcf + 256;         // 132: fcW[0..129), [129]=fcb, [130]=fcfb
    float*  sy    = sfc + 132;          // 64  [g][32]
    float*  slogS = sy + 64;            // 64
    float*  sEp   = slogS + 64;         // 16  [g][8]

    const int tid  = threadIdx.x;
    const int lane = tid & 31;
    const int warp = tid >> 5;
    const int bp   = blockIdx.x * 2;

    // ---- load phase ----
    for (int i = tid; i < 8192; i += 512)
        reinterpret_cast<uint4*>(sWhh)[i] =
            reinterpret_cast<const uint4*>(g_WhhH)[i];
    for (int i4 = tid; i4 < 2048; i4 += 512) {
        int r = i4 >> 5, c = i4 & 31;
        reinterpret_cast<float4*>(sEnc)[r * 33 + c] =
            reinterpret_cast<const float4*>(enc + (size_t)bp * 4096)[i4];
    }
    sWih[tid]  = Wih[tid];
    sbias[tid] = bih[tid] + bhh[tid];
    if (tid < 552) sHp[tid] = 0.f;
    if (tid < 292) reinterpret_cast<float*>(sHh)[tid] = 0.f;
    if (tid < 128) sW2[tid]  = W2[tid];
    if (tid < 256) sfcf[tid] = fcfW[tid];
    if (tid < 131)
        sfc[tid] = (tid < 129) ? fcW[tid] : (tid == 129) ? fcb[0] : fcfb[0];
    if (tid < 64) sy[tid] = yhist[(bp + (tid >> 5)) * 32 + (tid & 31)];
    __syncthreads();

    // ---- E1 = enc @ W1e^T + b1, in-CTA once, stored fp16 ----
    {
        int h = tid & 127, rq = tid >> 7;
        float acc[16];
        float bb = b1[h];
#pragma unroll
        for (int rr = 0; rr < 16; rr++) acc[rr] = bb;
        const float4* wsrc = reinterpret_cast<const float4*>(W1 + h * 384 + 256);
#pragma unroll
        for (int ch = 0; ch < 4; ch++) {
            float4 w[8];
#pragma unroll
            for (int kk = 0; kk < 8; kk++) w[kk] = wsrc[ch * 8 + kk];
#pragma unroll
            for (int rr = 0; rr < 16; rr++) {
                const float4* ev = reinterpret_cast<const float4*>(
                    sEnc + (rq * 16 + rr) * 132) + ch * 8;
                float s = 0.f;
#pragma unroll
                for (int kk = 0; kk < 8; kk++) {
                    float4 e = ev[kk];
                    s += w[kk].x * e.x + w[kk].y * e.y
                       + w[kk].z * e.z + w[kk].w * e.w;
                }
                acc[rr] += s;
            }
        }
#pragma unroll
        for (int rr = 0; rr < 16; rr++)
            sE1h[(rq * 16 + rr) * 128 + h] = __float2half(acc[rr]);
    }

    // ---- persistent A weights: thread (ja, qa) holds W1[ja][qa*64 .. +64)
    const int ja = (warp << 3) | (lane & 7);
    const int qa = lane >> 3;
    ulonglong2 w1r[16];   // 32 fp32-pairs
    {
        const ulonglong2* src =
            reinterpret_cast<const ulonglong2*>(W1 + ja * 384 + qa * 64);
#pragma unroll
        for (int i = 0; i < 16; i++) w1r[i] = src[i];
    }

    // F coordinates: k-half per warp-half, rows {rrF, rrF+256}, both batches
    const int khF = tid >> 8;
    const int rrF = tid & 255;
    __syncthreads();

    for (int step = 0; step < TT; step++) {
        // ---- A: u[g][ja] = hc[g] . W1[ja]  (fp16 hc shadow, fp32 math)
        {
            const uint4* hA = reinterpret_cast<const uint4*>(sHh + qa * HQH);
            const uint4* hB = reinterpret_cast<const uint4*>(sHh + HBH + qa * HQH);
            ULL a0 = 0, a1 = 0, c0 = 0, c1 = 0;
#pragma unroll
            for (int i = 0; i < 8; i += 2) {
                uint4 X = hA[i], Y = hB[i];
                ulonglong2 wA = w1r[2 * i], wB = w1r[2 * i + 1];
                a0 = fma2(wA.x, h2f2(X.x), a0); a0 = fma2(wA.y, h2f2(X.y), a0);
                a0 = fma2(wB.x, h2f2(X.z), a0); a0 = fma2(wB.y, h2f2(X.w), a0);
                a1 = fma2(wA.x, h2f2(Y.x), a1); a1 = fma2(wA.y, h2f2(Y.y), a1);
                a1 = fma2(wB.x, h2f2(Y.z), a1); a1 = fma2(wB.y, h2f2(Y.w), a1);
                uint4 X2 = hA[i + 1], Y2 = hB[i + 1];
                ulonglong2 wC = w1r[2 * i + 2], wD = w1r[2 * i + 3];
                c0 = fma2(wC.x, h2f2(X2.x), c0); c0 = fma2(wC.y, h2f2(X2.y), c0);
                c0 = fma2(wD.x, h2f2(X2.z), c0); c0 = fma2(wD.y, h2f2(X2.w), c0);
                c1 = fma2(wC.x, h2f2(Y2.x), c1); c1 = fma2(wC.y, h2f2(Y2.y), c1);
                c1 = fma2(wD.x, h2f2(Y2.z), c1); c1 = fma2(wD.y, h2f2(Y2.w), c1);
            }
            float2 p0 = unpack2(a0), p1 = unpack2(c0);
            float2 q0 = unpack2(a1), q1 = unpack2(c1);
            float s0 = p0.x + p0.y + p1.x + p1.y;
            float s1 = q0.x + q0.y + q1.x + q1.y;
            s0 += __shfl_xor_sync(0xffffffffu, s0, 8);
            s0 += __shfl_xor_sync(0xffffffffu, s0, 16);
            s1 += __shfl_xor_sync(0xffffffffu, s1, 8);
            s1 += __shfl_xor_sync(0xffffffffu, s1, 16);
            if (lane < 8) { su[ja] = s0; su[128 + ja] = s1; }
        }
        __syncthreads();

        // ---- B: 64 logits; warp covers 4 rows via 8-lane groups (fp16 E1)
        {
            int c8 = lane & 7, pr = lane >> 3;
            int p  = (warp << 2) | pr;
            int pg = p >> 5;
            const uint4* e1r = reinterpret_cast<const uint4*>(sE1h)
                             + p * 16 + c8 * 2;
            const float4* ur = reinterpret_cast<const float4*>(su)
                             + pg * 32 + c8 * 4;
            const float4* wr = reinterpret_cast<const float4*>(sW2) + c8 * 4;
            uint4 U0 = e1r[0], U1 = e1r[1];
            float4 u0 = ur[0], u1 = ur[1], u2 = ur[2], u3 = ur[3];
            float4 w0 = wr[0], w1 = wr[1], w2 = wr[2], w3 = wr[3];
            float s = 0.f;
            float2 e;
            e = h2tof2(U0.x); s += fast_tanh(e.x + u0.x) * w0.x + fast_tanh(e.y + u0.y) * w0.y;
            e = h2tof2(U0.y); s += fast_tanh(e.x + u0.z) * w0.z + fast_tanh(e.y + u0.w) * w0.w;
            e = h2tof2(U0.z); s += fast_tanh(e.x + u1.x) * w1.x + fast_tanh(e.y + u1.y) * w1.y;
            e = h2tof2(U0.w); s += fast_tanh(e.x + u1.z) * w1.z + fast_tanh(e.y + u1.w) * w1.w;
            e = h2tof2(U1.x); s += fast_tanh(e.x + u2.x) * w2.x + fast_tanh(e.y + u2.y) * w2.y;
            e = h2tof2(U1.y); s += fast_tanh(e.x + u2.z) * w2.z + fast_tanh(e.y + u2.w) * w2.w;
            e = h2tof2(U1.z); s += fast_tanh(e.x + u3.x) * w3.x + fast_tanh(e.y + u3.y) * w3.y;
            e = h2tof2(U1.w); s += fast_tanh(e.x + u3.z) * w3.z + fast_tanh(e.y + u3.w) * w3.w;
            s += __shfl_xor_sync(0xffffffffu, s, 1);
            s += __shfl_xor_sync(0xffffffffu, s, 2);
            s += __shfl_xor_sync(0xffffffffu, s, 4);
            if (c8 == 0) slogS[p] = s;
        }
        __syncthreads();

        // ---- C+D+E-partials (softmax in regs, ctx, y partials)
        {
            int g  = warp >> 3;
            int wb = warp & 7;
            float l  = slogS[g * 32 + lane];
            float mx = l;
#pragma unroll
            for (int o = 16; o > 0; o >>= 1)
                mx = fmaxf(mx, __shfl_xor_sync(0xffffffffu, mx, o));
            float e   = __expf(l - mx);
            float sum = e;
#pragma unroll
            for (int o = 16; o > 0; o >>= 1)
                sum += __shfl_xor_sync(0xffffffffu, sum, o);
            float a = e / sum;

            int jp = (wb << 3) | (lane & 7);
            int ts = lane >> 3;
            const ULL* e2 = reinterpret_cast<const ULL*>(sEnc) + g * 2112 + jp;
            ULL acc = 0;
#pragma unroll
            for (int i = 0; i < 8; i++) {
                int t = ts * 8 + i;
                ULL av = pack2(__shfl_sync(0xffffffffu, a, t));
                acc = fma2(av, e2[t * 66], acc);
            }
            float2 v = unpack2(acc);
            v.x += __shfl_xor_sync(0xffffffffu, v.x, 8);
            v.y += __shfl_xor_sync(0xffffffffu, v.y, 8);
            v.x += __shfl_xor_sync(0xffffffffu, v.x, 16);
            v.y += __shfl_xor_sync(0xffffffffu, v.y, 16);
            float px = 0.f;
            if (ts == 0) {
                reinterpret_cast<float2*>(sctxC)[g * 64 + jp] = v;
                px = v.x * sfc[2 * jp] + v.y * sfc[2 * jp + 1];
            }
            px += __shfl_xor_sync(0xffffffffu, px, 1);
            px += __shfl_xor_sync(0xffffffffu, px, 2);
            px += __shfl_xor_sync(0xffffffffu, px, 4);
            if (lane == 0) sEp[g * 8 + wb] = px;
        }
        // ---- F: gate partials, fp16 weights x fp16 h shadow, fp32 accum.
        //      (reads prev-step h, no barrier needed after CD)
        {
            const uint4* wp = reinterpret_cast<const uint4*>(sWhh)
                            + (khF << 3) * 512 + rrF;
            const __half* hb0 = sHh + khF * HQH;         // batch0 h, quarter khF
            const __half* hb1 = sHh + HBH + khF * HQH;   // batch1
            ULL a0 = 0, a1 = 0, c0 = 0, c1 = 0;
#pragma unroll
            for (int mm = 0; mm < 8; mm++) {
                uint4 wA = wp[mm * 512];
                uint4 wB = wp[mm * 512 + 256];
                uint4 X  = *reinterpret_cast<const uint4*>(hb0 + mm * 8);
                uint4 Y  = *reinterpret_cast<const uint4*>(hb1 + mm * 8);
                ULL x0 = h2f2(X.x), x1 = h2f2(X.y), x2 = h2f2(X.z), x3 = h2f2(X.w);
                ULL y0 = h2f2(Y.x), y1 = h2f2(Y.y), y2 = h2f2(Y.z), y3 = h2f2(Y.w);
                ULL w0 = h2f2(wA.x), w1 = h2f2(wA.y), w2 = h2f2(wA.z), w3 = h2f2(wA.w);
                a0 = fma2(w0, x0, a0); a0 = fma2(w1, x1, a0);
                a0 = fma2(w2, x2, a0); a0 = fma2(w3, x3, a0);
                a1 = fma2(w0, y0, a1); a1 = fma2(w1, y1, a1);
                a1 = fma2(w2, y2, a1); a1 = fma2(w3, y3, a1);
                ULL v0 = h2f2(wB.x), v1 = h2f2(wB.y), v2 = h2f2(wB.z), v3 = h2f2(wB.w);
                c0 = fma2(v0, x0, c0); c0 = fma2(v1, x1, c0);
                c0 = fma2(v2, x2, c0); c0 = fma2(v3, x3, c0);
                c1 = fma2(v0, y0, c1); c1 = fma2(v1, y1, c1);
                c1 = fma2(v2, y2, c1); c1 = fma2(v3, y3, c1);
            }
            float2 u0 = unpack2(a0), u1 = unpack2(a1);
            float2 t0 = unpack2(c0), t1 = unpack2(c1);
            float* P = sgp + (khF << 10);
            P[rrF]             = u0.x + u0.y;
            P[512 + rrF]       = u1.x + u1.y;
            P[rrF + 256]       = t0.x + t0.y;
            P[512 + rrF + 256] = t1.x + t1.y;
        }
        __syncthreads();

        // ---- G: y_tilde combine + LSTM cell (fp32 master, fp16 shadow)
        if (tid < 256) {
            int j = tid & 127, g = tid >> 7;
            const float* ep = sEp + g * 8;
            float y = ep[0] + ep[1] + ep[2] + ep[3]
                    + ep[4] + ep[5] + ep[6] + ep[7]
                    + sy[g * 32 + step] * sfc[128] + sfc[129];
            float gv[4];
#pragma unroll
            for (int q = 0; q < 4; q++) {
                int r = q * 128 + j;
                gv[q] = sgp[g * 512 + r] + sgp[1024 + g * 512 + r]
                      + sbias[r] + y * sWih[r];
            }
            int hq = j >> 6, ho = j & 63;
            float* hb = sHp + g * HB;
            float c_old = hb[(2 + hq) * HQ + ho];
            float si = fast_sig(gv[0]);
            float sf = fast_sig(gv[1]);
            float so = fast_sig(gv[3]);
            float cn = sf * c_old + si * fast_tanh(gv[2]);
            float hn = so * fast_tanh(cn);
            hb[(2 + hq) * HQ + ho] = cn;
            hb[hq * HQ + ho]       = hn;
            __half* hh = sHh + g * HBH;
            hh[hq * HQH + ho]       = __float2half(hn);
            hh[(2 + hq) * HQH + ho] = __float2half(cn);
        }
        __syncthreads();
    }

    // ---- final: out[b] = [h, ctx] . fcfW + fcfb + y_history[b, 31]
    if (warp < 2) {
        int g = warp;
        float4 hv = reinterpret_cast<const float4*>(sHp + g * HB)
                        [(lane >> 4) * 17 + (lane & 15)];
        float4 f1 = reinterpret_cast<const float4*>(sfcf)[lane];
        float4 cv = reinterpret_cast<const float4*>(sctxC + g * 128)[lane];
        float4 f2 = reinterpret_cast<const float4*>(sfcf + 128)[lane];
        float s = hv.x * f1.x + hv.y * f1.y + hv.z * f1.z + hv.w * f1.w
                + cv.x * f2.x + cv.y * f2.y + cv.z * f2.z + cv.w * f2.w;
#pragma unroll
        for (int o = 16; o > 0; o >>= 1)
            s += __shfl_xor_sync(0xffffffffu, s, o);
        if (lane == 0)
            out[bp + g] = s + sfc[130] + sy[g * 32 + 31];
    }
}

// ---------------------------------------------------------------------------
extern "C" void kernel_launch(void* const* d_in, const int* in_sizes, int n_in,
                              void* d_out, int out_size)
{
    const float* enc  = (const float*)d_in[0];
    const float* yh   = (const float*)d_in[1];
    const float* W1   = (const float*)d_in[2];
    const float* b1   = (const float*)d_in[3];
    const float* W2   = (const float*)d_in[4];
    // d_in[5] = attn_b2 : constant shift, cancels in softmax
    const float* Wih  = (const float*)d_in[6];
    const float* Whh  = (const float*)d_in[7];
    const float* bih  = (const float*)d_in[8];
    const float* bhh  = (const float*)d_in[9];
    const float* fcW  = (const float*)d_in[10];
    const float* fcb  = (const float*)d_in[11];
    const float* fcfW = (const float*)d_in[12];
    const float* fcfb = (const float*)d_in[13];
    float* out = (float*)d_out;

    const size_t smem_floats = 32768 + 8448 + 4096 + 292 + 552 + 2048
                             + 256 + 256 + 512 + 512 + 128 + 256 + 132
                             + 64 + 64 + 16;
    const size_t smem = smem_floats * sizeof(float);   // ~201.6 KB

    cudaFuncSetAttribute(decoder_kernel,
                         cudaFuncAttributeMaxDynamicSharedMemorySize, (int)smem);
    cudaFuncSetAttribute(decoder_kernel,
                         cudaFuncAttributePreferredSharedMemoryCarveout, 100);

    whh_prep<<<8, 128>>>(Whh);
    decoder_kernel<<<128, 512, smem>>>(enc, yh, W1, b1, W2, Wih, bih, bhh,
                                       fcW, fcb, fcfW, fcfb, out);
}

// round 10
// speedup vs baseline: 1.4285x; 1.4285x over previous
#include <cuda_runtime.h>
#include <cuda_fp16.h>

#define BB 256
#define TT 32

typedef unsigned long long ULL;

// Device-global scratch: Whh fp16 row-major padded [512][136] (272B rows)
__device__ __half g_WhhH[512 * 136];

__device__ __forceinline__ float fast_tanh(float x) {
    float y;
    asm("tanh.approx.f32 %0, %1;" : "=f"(y) : "f"(x));
    return y;
}
__device__ __forceinline__ float fast_sig(float x) {
    return 0.5f + 0.5f * fast_tanh(0.5f * x);
}
__device__ __forceinline__ ULL fma2(ULL a, ULL b, ULL c) {
    ULL d;
    asm("fma.rn.f32x2 %0, %1, %2, %3;" : "=l"(d) : "l"(a), "l"(b), "l"(c));
    return d;
}
__device__ __forceinline__ float2 unpack2(ULL v) {
    float2 r;
    asm("mov.b64 {%0, %1}, %2;" : "=f"(r.x), "=f"(r.y) : "l"(v));
    return r;
}
__device__ __forceinline__ ULL pack2(float a) {
    ULL v;
    asm("mov.b64 %0, {%1, %1};" : "=l"(v) : "f"(a));
    return v;
}

// fp32 master hc layout: quarters of 64 floats at stride 68; batch stride 272.
#define HQ 68
#define HB 272

// ---------------------------------------------------------------------------
// Prep: Whh fp32 -> fp16 row-major padded [512][136]
// ---------------------------------------------------------------------------
__global__ void __launch_bounds__(128)
whh_prep(const float* __restrict__ Whh)   // [512,128]
{
    int base = blockIdx.x * 8704;
    for (int i = base + threadIdx.x; i < base + 8704; i += 128) {
        int r = i / 136, k = i % 136;
        g_WhhH[i] = __float2half((k < 128) ? Whh[r * 128 + k] : 0.f);
    }
}

// ---------------------------------------------------------------------------
// Main: 128 blocks x 512 threads, 2 batches/block. 4 barriers per step.
// Gates GEMV on tensor cores (m16n8k16), Whh fp16 resident in SMEM.
// ---------------------------------------------------------------------------
__global__ void __launch_bounds__(512, 1)
decoder_kernel(const float* __restrict__ enc,     // [B,32,128]
               const float* __restrict__ yhist,   // [B,32]
               const float* __restrict__ W1,      // [128,384] cols [h|c|enc]
               const float* __restrict__ b1,      // [128]
               const float* __restrict__ W2,      // [128]
               const float* __restrict__ Wih,     // [512]
               const float* __restrict__ bih,     // [512]
               const float* __restrict__ bhh,     // [512]
               const float* __restrict__ fcW,     // [129]
               const float* __restrict__ fcb,     // [1]
               const float* __restrict__ fcfW,    // [256]
               const float* __restrict__ fcfb,    // [1]
               float* __restrict__ out)           // [256]
{
    extern __shared__ float sm[];
    __half* sWh   = (__half*)sm;        // [512][136] fp16 = 34816 fl
    float*  sEnc  = sm + 34816;         // 8448 [64 rows][132]
    float*  sE1   = sEnc + 8448;        // 8448 [64 rows][132]
    float*  sHp   = sE1 + 8448;         // 552  fp32 master hc [g][q][68]
    __half* sHh   = (__half*)(sHp + 552); // [8][136] fp16 h for MMA B = 544 fl
    float*  sgates= sHp + 552 + 544;    // 1024 [g][512]
    float*  su    = sgates + 1024;      // 256  [g][128]
    float*  sctxC = su + 256;           // 256  [g][128]
    float*  sWih  = sctxC + 256;        // 512
    float*  sbias = sWih + 512;         // 512
    float*  sW2   = sbias + 512;        // 128
    float*  sfcf  = sW2 + 128;          // 256
    float*  sfc   = sfcf + 256;         // 132: fcW[0..129), [129]=fcb, [130]=fcfb
    float*  sy    = sfc + 132;          // 64  [g][32]
    float*  slogS = sy + 64;            // 64
    float*  sEp   = slogS + 64;         // 16  [g][8]

    const int tid  = threadIdx.x;
    const int lane = tid & 31;
    const int warp = tid >> 5;
    const int bp   = blockIdx.x * 2;

    // ---- load phase ----
    for (int i = tid; i < 8704; i += 512)
        reinterpret_cast<uint4*>(sWh)[i] =
            reinterpret_cast<const uint4*>(g_WhhH)[i];
    for (int i4 = tid; i4 < 2048; i4 += 512) {
        int r = i4 >> 5, c = i4 & 31;
        reinterpret_cast<float4*>(sEnc)[r * 33 + c] =
            reinterpret_cast<const float4*>(enc + (size_t)bp * 4096)[i4];
    }
    sWih[tid]  = Wih[tid];
    sbias[tid] = bih[tid] + bhh[tid];
    if (tid < 552) sHp[tid] = 0.f;
    if (tid < 544) reinterpret_cast<float*>(sHh)[tid] = 0.f;  // rows 2-7 stay 0
    if (tid < 128) sW2[tid]  = W2[tid];
    if (tid < 256) sfcf[tid] = fcfW[tid];
    if (tid < 131)
        sfc[tid] = (tid < 129) ? fcW[tid] : (tid == 129) ? fcb[0] : fcfb[0];
    if (tid < 64) sy[tid] = yhist[(bp + (tid >> 5)) * 32 + (tid & 31)];
    __syncthreads();

    // ---- E1 = enc @ W1e^T + b1, in-CTA once ----
    {
        int h = tid & 127, rq = tid >> 7;
        float acc[16];
        float bb = b1[h];
#pragma unroll
        for (int rr = 0; rr < 16; rr++) acc[rr] = bb;
        const float4* wsrc = reinterpret_cast<const float4*>(W1 + h * 384 + 256);
#pragma unroll
        for (int ch = 0; ch < 4; ch++) {
            float4 w[8];
#pragma unroll
            for (int kk = 0; kk < 8; kk++) w[kk] = wsrc[ch * 8 + kk];
#pragma unroll
            for (int rr = 0; rr < 16; rr++) {
                const float4* ev = reinterpret_cast<const float4*>(
                    sEnc + (rq * 16 + rr) * 132) + ch * 8;
                float s = 0.f;
#pragma unroll
                for (int kk = 0; kk < 8; kk++) {
                    float4 e = ev[kk];
                    s += w[kk].x * e.x + w[kk].y * e.y
                       + w[kk].z * e.z + w[kk].w * e.w;
                }
                acc[rr] += s;
            }
        }
#pragma unroll
        for (int rr = 0; rr < 16; rr++)
            sE1[(rq * 16 + rr) * 132 + h] = acc[rr];
    }

    // ---- persistent A weights: thread (ja, qa) holds W1[ja][qa*64 .. +64)
    const int ja = (warp << 3) | (lane & 7);
    const int qa = lane >> 3;
    ulonglong2 w1r[16];
    {
        const ulonglong2* src =
            reinterpret_cast<const ulonglong2*>(W1 + ja * 384 + qa * 64);
#pragma unroll
        for (int i = 0; i < 16; i++) w1r[i] = src[i];
    }

    // ---- MMA constants for F ----
    const int tg  = lane & 3;     // thread-in-group (k / col selector)
    const int g8  = lane >> 2;    // group id (row / n selector)
    // ldmatrix base for this warp's two 16-row tiles (rows 32w.. / 32w+16..)
    const unsigned whBase = (unsigned)__cvta_generic_to_shared(sWh);
    const unsigned sA0 = whBase +
        (((warp << 5) | (lane & 15)) * 136 + ((lane >> 4) << 3)) * 2;
    const unsigned sA1 = sA0 + 16 * 136 * 2;
    __syncthreads();

    for (int step = 0; step < TT; step++) {
        // ---- A: u[g][ja] = hc[g] . W1[ja]  (padded quarters: conflict-free)
        {
            const ulonglong2* h0 =
                reinterpret_cast<const ulonglong2*>(sHp) + qa * 17;
            const ulonglong2* h1 =
                reinterpret_cast<const ulonglong2*>(sHp + HB) + qa * 17;
            ULL a0 = 0, a1 = 0, c0 = 0, c1 = 0;
#pragma unroll
            for (int i = 0; i < 16; i += 2) {
                ulonglong2 w  = w1r[i],     x  = h0[i],     y  = h1[i];
                a0 = fma2(w.x, x.x, a0);  a0 = fma2(w.y, x.y, a0);
                a1 = fma2(w.x, y.x, a1);  a1 = fma2(w.y, y.y, a1);
                ulonglong2 w2 = w1r[i + 1], x2 = h0[i + 1], y2 = h1[i + 1];
                c0 = fma2(w2.x, x2.x, c0); c0 = fma2(w2.y, x2.y, c0);
                c1 = fma2(w2.x, y2.x, c1); c1 = fma2(w2.y, y2.y, c1);
            }
            float2 p0 = unpack2(a0), p1 = unpack2(c0);
            float2 q0 = unpack2(a1), q1 = unpack2(c1);
            float s0 = p0.x + p0.y + p1.x + p1.y;
            float s1 = q0.x + q0.y + q1.x + q1.y;
            s0 += __shfl_xor_sync(0xffffffffu, s0, 8);
            s0 += __shfl_xor_sync(0xffffffffu, s0, 16);
            s1 += __shfl_xor_sync(0xffffffffu, s1, 8);
            s1 += __shfl_xor_sync(0xffffffffu, s1, 16);
            if (lane < 8) { su[ja] = s0; su[128 + ja] = s1; }
        }
        __syncthreads();

        // ---- B: 64 logits; warp covers 4 rows via 8-lane groups
        {
            int c8 = lane & 7, pr = lane >> 3;
            int p  = (warp << 2) | pr;
            int pg = p >> 5, pt = p & 31;
            const float4* e1r = reinterpret_cast<const float4*>(
                sE1 + (pg * 32 + pt) * 132);
            const float4* ur  = reinterpret_cast<const float4*>(su) + pg * 32;
            const float4* wr  = reinterpret_cast<const float4*>(sW2);
            float s = 0.f;
#pragma unroll
            for (int c = 0; c < 4; c++) {
                int idx = c * 8 + c8;
                float4 e = e1r[idx], u = ur[idx], w = wr[idx];
                s += fast_tanh(e.x + u.x) * w.x + fast_tanh(e.y + u.y) * w.y
                   + fast_tanh(e.z + u.z) * w.z + fast_tanh(e.w + u.w) * w.w;
            }
            s += __shfl_xor_sync(0xffffffffu, s, 1);
            s += __shfl_xor_sync(0xffffffffu, s, 2);
            s += __shfl_xor_sync(0xffffffffu, s, 4);
            if (c8 == 0) slogS[p] = s;
        }
        // ---- F: gates = Whh @ h on tensor cores. Warp w -> rows 32w..32w+31.
        //      Reads prev-step h (fp16 shadow); overlaps with B (no barrier).
        {
            float d00 = 0.f, d01 = 0.f, d02 = 0.f, d03 = 0.f;
            float d10 = 0.f, d11 = 0.f, d12 = 0.f, d13 = 0.f;
            const __half* bb = sHh + g8 * 136 + tg * 2;
#pragma unroll
            for (int kt = 0; kt < 8; kt++) {
                unsigned a0, a1, a2, a3, e0, e1, e2, e3;
                asm volatile(
                    "ldmatrix.sync.aligned.m8n8.x4.shared.b16 {%0,%1,%2,%3}, [%4];"
                    : "=r"(a0), "=r"(a1), "=r"(a2), "=r"(a3)
                    : "r"(sA0 + kt * 32));
                asm volatile(
                    "ldmatrix.sync.aligned.m8n8.x4.shared.b16 {%0,%1,%2,%3}, [%4];"
                    : "=r"(e0), "=r"(e1), "=r"(e2), "=r"(e3)
                    : "r"(sA1 + kt * 32));
                unsigned b0 = *reinterpret_cast<const unsigned*>(bb + kt * 16);
                unsigned b1 = *reinterpret_cast<const unsigned*>(bb + kt * 16 + 8);
                asm volatile(
                    "mma.sync.aligned.m16n8k16.row.col.f32.f16.f16.f32 "
                    "{%0,%1,%2,%3}, {%4,%5,%6,%7}, {%8,%9}, {%0,%1,%2,%3};"
                    : "+f"(d00), "+f"(d01), "+f"(d02), "+f"(d03)
                    : "r"(a0), "r"(a1), "r"(a2), "r"(a3), "r"(b0), "r"(b1));
                asm volatile(
                    "mma.sync.aligned.m16n8k16.row.col.f32.f16.f16.f32 "
                    "{%0,%1,%2,%3}, {%4,%5,%6,%7}, {%8,%9}, {%0,%1,%2,%3};"
                    : "+f"(d10), "+f"(d11), "+f"(d12), "+f"(d13)
                    : "r"(e0), "r"(e1), "r"(e2), "r"(e3), "r"(b0), "r"(b1));
            }
            if (tg == 0) {   // cols 0,1 = batches 0,1
                int r0 = (warp << 5) | g8;
                sgates[r0]            = d00;  sgates[512 + r0]      = d01;
                sgates[r0 + 8]        = d02;  sgates[512 + r0 + 8]  = d03;
                sgates[r0 + 16]       = d10;  sgates[512 + r0 + 16] = d11;
                sgates[r0 + 24]       = d12;  sgates[512 + r0 + 24] = d13;
            }
        }
        __syncthreads();

        // ---- C+D+E-partials (softmax in regs, ctx, y partials)
        {
            int g  = warp >> 3;
            int wb = warp & 7;
            float l  = slogS[g * 32 + lane];
            float mx = l;
#pragma unroll
            for (int o = 16; o > 0; o >>= 1)
                mx = fmaxf(mx, __shfl_xor_sync(0xffffffffu, mx, o));
            float e   = __expf(l - mx);
            float sum = e;
#pragma unroll
            for (int o = 16; o > 0; o >>= 1)
                sum += __shfl_xor_sync(0xffffffffu, sum, o);
            float a = e / sum;

            int jp = (wb << 3) | (lane & 7);
            int ts = lane >> 3;
            const ULL* e2 = reinterpret_cast<const ULL*>(sEnc) + g * 2112 + jp;
            ULL acc = 0;
#pragma unroll
            for (int i = 0; i < 8; i++) {
                int t = ts * 8 + i;
                ULL av = pack2(__shfl_sync(0xffffffffu, a, t));
                acc = fma2(av, e2[t * 66], acc);
            }
            float2 v = unpack2(acc);
            v.x += __shfl_xor_sync(0xffffffffu, v.x, 8);
            v.y += __shfl_xor_sync(0xffffffffu, v.y, 8);
            v.x += __shfl_xor_sync(0xffffffffu, v.x, 16);
            v.y += __shfl_xor_sync(0xffffffffu, v.y, 16);
            float px = 0.f;
            if (ts == 0) {
                reinterpret_cast<float2*>(sctxC)[g * 64 + jp] = v;
                px = v.x * sfc[2 * jp] + v.y * sfc[2 * jp + 1];
            }
            px += __shfl_xor_sync(0xffffffffu, px, 1);
            px += __shfl_xor_sync(0xffffffffu, px, 2);
            px += __shfl_xor_sync(0xffffffffu, px, 4);
            if (lane == 0) sEp[g * 8 + wb] = px;
        }
        __syncthreads();

        // ---- G: y_tilde combine + LSTM cell (fp32 master + fp16 h shadow)
        if (tid < 256) {
            int j = tid & 127, g = tid >> 7;
            const float* ep = sEp + g * 8;
            float y = ep[0] + ep[1] + ep[2] + ep[3]
                    + ep[4] + ep[5] + ep[6] + ep[7]
                    + sy[g * 32 + step] * sfc[128] + sfc[129];
            float gv[4];
#pragma unroll
            for (int q = 0; q < 4; q++) {
                int r = q * 128 + j;
                gv[q] = sgates[g * 512 + r] + sbias[r] + y * sWih[r];
            }
            int hq = j >> 6, ho = j & 63;
            float* hb = sHp + g * HB;
            float c_old = hb[(2 + hq) * HQ + ho];
            float si = fast_sig(gv[0]);
            float sf = fast_sig(gv[1]);
            float so = fast_sig(gv[3]);
            float cn = sf * c_old + si * fast_tanh(gv[2]);
            float hn = so * fast_tanh(cn);
            hb[(2 + hq) * HQ + ho] = cn;
            hb[hq * HQ + ho]       = hn;
            sHh[g * 136 + j] = __float2half(hn);   // MMA B operand
        }
        __syncthreads();
    }

    // ---- final: out[b] = [h, ctx] . fcfW + fcfb + y_history[b, 31]
    if (warp < 2) {
        int g = warp;
        float4 hv = reinterpret_cast<const float4*>(sHp + g * HB)
                        [(lane >> 4) * 17 + (lane & 15)];
        float4 f1 = reinterpret_cast<const float4*>(sfcf)[lane];
        float4 cv = reinterpret_cast<const float4*>(sctxC + g * 128)[lane];
        float4 f2 = reinterpret_cast<const float4*>(sfcf + 128)[lane];
        float s = hv.x * f1.x + hv.y * f1.y + hv.z * f1.z + hv.w * f1.w
                + cv.x * f2.x + cv.y * f2.y + cv.z * f2.z + cv.w * f2.w;
#pragma unroll
        for (int o = 16; o > 0; o >>= 1)
            s += __shfl_xor_sync(0xffffffffu, s, o);
        if (lane == 0)
            out[bp + g] = s + sfc[130] + sy[g * 32 + 31];
    }
}

// ---------------------------------------------------------------------------
extern "C" void kernel_launch(void* const* d_in, const int* in_sizes, int n_in,
                              void* d_out, int out_size)
{
    const float* enc  = (const float*)d_in[0];
    const float* yh   = (const float*)d_in[1];
    const float* W1   = (const float*)d_in[2];
    const float* b1   = (const float*)d_in[3];
    const float* W2   = (const float*)d_in[4];
    // d_in[5] = attn_b2 : constant shift, cancels in softmax
    const float* Wih  = (const float*)d_in[6];
    const float* Whh  = (const float*)d_in[7];
    const float* bih  = (const float*)d_in[8];
    const float* bhh  = (const float*)d_in[9];
    const float* fcW  = (const float*)d_in[10];
    const float* fcb  = (const float*)d_in[11];
    const float* fcfW = (const float*)d_in[12];
    const float* fcfb = (const float*)d_in[13];
    float* out = (float*)d_out;

    const size_t smem_floats = 34816 + 8448 + 8448 + 552 + 544 + 1024
                             + 256 + 256 + 512 + 512 + 128 + 256 + 132
                             + 64 + 64 + 16;
    const size_t smem = smem_floats * sizeof(float);   // ~218.9 KB

    cudaFuncSetAttribute(decoder_kernel,
                         cudaFuncAttributeMaxDynamicSharedMemorySize, (int)smem);
    cudaFuncSetAttribute(decoder_kernel,
                         cudaFuncAttributePreferredSharedMemoryCarveout, 100);

    whh_prep<<<8, 128>>>(Whh);
    decoder_kernel<<<128, 512, smem>>>(enc, yh, W1, b1, W2, Wih, bih, bhh,
                                       fcW, fcb, fcfW, fcfb, out);
}

// round 11
// speedup vs baseline: 1.5349x; 1.0745x over previous
#include <cuda_runtime.h>
#include <cuda_fp16.h>

#define BB 256
#define TT 32

typedef unsigned long long ULL;

// Device-global scratch: Whh fp16 row-major padded [512][136] (272B rows)
__device__ __half g_WhhH[512 * 136];

__device__ __forceinline__ float fast_tanh(float x) {
    float y;
    asm("tanh.approx.f32 %0, %1;" : "=f"(y) : "f"(x));
    return y;
}
__device__ __forceinline__ float fast_sig(float x) {
    return 0.5f + 0.5f * fast_tanh(0.5f * x);
}
__device__ __forceinline__ ULL fma2(ULL a, ULL b, ULL c) {
    ULL d;
    asm("fma.rn.f32x2 %0, %1, %2, %3;" : "=l"(d) : "l"(a), "l"(b), "l"(c));
    return d;
}
__device__ __forceinline__ float2 unpack2(ULL v) {
    float2 r;
    asm("mov.b64 {%0, %1}, %2;" : "=f"(r.x), "=f"(r.y) : "l"(v));
    return r;
}
__device__ __forceinline__ ULL pack2(float a) {
    ULL v;
    asm("mov.b64 %0, {%1, %1};" : "=l"(v) : "f"(a));
    return v;
}
__device__ __forceinline__ unsigned packh2(float x, float y) {
    __half2 h = __floats2half2_rn(x, y);
    return *reinterpret_cast<unsigned*>(&h);
}

#define MMA16816(d0,d1,d2,d3,a0,a1,a2,a3,b0,b1)                              \
    asm volatile(                                                            \
        "mma.sync.aligned.m16n8k16.row.col.f32.f16.f16.f32 "                 \
        "{%0,%1,%2,%3}, {%4,%5,%6,%7}, {%8,%9}, {%0,%1,%2,%3};"              \
        : "+f"(d0), "+f"(d1), "+f"(d2), "+f"(d3)                             \
        : "r"(a0), "r"(a1), "r"(a2), "r"(a3), "r"(b0), "r"(b1))

// fp32 master hc layout: quarters of 64 floats at stride 68; batch stride 272.
#define HQ 68
#define HB 272
// fp16 hc shadow: rows = batch (8 rows, 2 real), 264 halves per row.
#define HCS 264

// ---------------------------------------------------------------------------
// Prep: Whh fp32 -> fp16 row-major padded [512][136]
// ---------------------------------------------------------------------------
__global__ void __launch_bounds__(128)
whh_prep(const float* __restrict__ Whh)   // [512,128]
{
    int base = blockIdx.x * 8704;
    for (int i = base + threadIdx.x; i < base + 8704; i += 128) {
        int r = i / 136, k = i % 136;
        g_WhhH[i] = __float2half((k < 128) ? Whh[r * 128 + k] : 0.f);
    }
}

// ---------------------------------------------------------------------------
// Main: 128 blocks x 512 threads, 2 batches/block. 4 barriers per step.
// A and F both on tensor cores; W1_hc fragments live in registers.
// ---------------------------------------------------------------------------
__global__ void __launch_bounds__(512, 1)
decoder_kernel(const float* __restrict__ enc,     // [B,32,128]
               const float* __restrict__ yhist,   // [B,32]
               const float* __restrict__ W1,      // [128,384] cols [h|c|enc]
               const float* __restrict__ b1,      // [128]
               const float* __restrict__ W2,      // [128]
               const float* __restrict__ Wih,     // [512]
               const float* __restrict__ bih,     // [512]
               const float* __restrict__ bhh,     // [512]
               const float* __restrict__ fcW,     // [129]
               const float* __restrict__ fcb,     // [1]
               const float* __restrict__ fcfW,    // [256]
               const float* __restrict__ fcfb,    // [1]
               float* __restrict__ out)           // [256]
{
    extern __shared__ float sm[];
    __half* sWh   = (__half*)sm;          // [512][136] fp16 = 34816 fl
    float*  sEnc  = sm + 34816;           // 8448 [64 rows][132]
    float*  sE1   = sEnc + 8448;          // 8448 [64 rows][132]
    float*  sHp   = sE1 + 8448;           // 552  fp32 master hc [g][q][68]
    __half* sHch  = (__half*)(sHp + 552); // [8][264] fp16 hc shadow = 1056 fl
    float*  sgates= sHp + 552 + 1056;     // 1024 [g][512]
    float*  sup   = sgates + 1024;        // 528  [kh][g][132] u partials
    float*  sctxC = sup + 528;            // 256  [g][128]
    float*  sWih  = sctxC + 256;          // 512
    float*  sbias = sWih + 512;           // 512
    float*  sW2   = sbias + 512;          // 128
    float*  sfcf  = sW2 + 128;            // 256
    float*  sfc   = sfcf + 256;           // 132: fcW[0..129), [129]=fcb, [130]=fcfb
    float*  sy    = sfc + 132;            // 64  [g][32]
    float*  slogS = sy + 64;              // 64
    float*  sEp   = slogS + 64;           // 16  [g][8]

    const int tid  = threadIdx.x;
    const int lane = tid & 31;
    const int warp = tid >> 5;
    const int bp   = blockIdx.x * 2;

    // MMA lane coordinates
    const int tg = lane & 3;     // quad id (k selector)
    const int g8 = lane >> 2;    // group id (row / col-n selector)

    // ---- load phase ----
    for (int i = tid; i < 8704; i += 512)
        reinterpret_cast<uint4*>(sWh)[i] =
            reinterpret_cast<const uint4*>(g_WhhH)[i];
    for (int i4 = tid; i4 < 2048; i4 += 512) {
        int r = i4 >> 5, c = i4 & 31;
        reinterpret_cast<float4*>(sEnc)[r * 33 + c] =
            reinterpret_cast<const float4*>(enc + (size_t)bp * 4096)[i4];
    }
    sWih[tid]  = Wih[tid];
    sbias[tid] = bih[tid] + bhh[tid];
    if (tid < 552) sHp[tid] = 0.f;
    for (int i = tid; i < 1056; i += 512)
        reinterpret_cast<float*>(sHch)[i] = 0.f;
    if (tid < 128) sW2[tid]  = W2[tid];
    if (tid < 256) sfcf[tid] = fcfW[tid];
    if (tid < 131)
        sfc[tid] = (tid < 129) ? fcW[tid] : (tid == 129) ? fcb[0] : fcfb[0];
    if (tid < 64) sy[tid] = yhist[(bp + (tid >> 5)) * 32 + (tid & 31)];
    __syncthreads();

    // ---- E1 = enc @ W1e^T + b1, in-CTA once ----
    {
        int h = tid & 127, rq = tid >> 7;
        float acc[16];
        float bb = b1[h];
#pragma unroll
        for (int rr = 0; rr < 16; rr++) acc[rr] = bb;
        const float4* wsrc = reinterpret_cast<const float4*>(W1 + h * 384 + 256);
#pragma unroll
        for (int ch = 0; ch < 4; ch++) {
            float4 w[8];
#pragma unroll
            for (int kk = 0; kk < 8; kk++) w[kk] = wsrc[ch * 8 + kk];
#pragma unroll
            for (int rr = 0; rr < 16; rr++) {
                const float4* ev = reinterpret_cast<const float4*>(
                    sEnc + (rq * 16 + rr) * 132) + ch * 8;
                float s = 0.f;
#pragma unroll
                for (int kk = 0; kk < 8; kk++) {
                    float4 e = ev[kk];
                    s += w[kk].x * e.x + w[kk].y * e.y
                       + w[kk].z * e.z + w[kk].w * e.w;
                }
                acc[rr] += s;
            }
        }
#pragma unroll
        for (int rr = 0; rr < 16; rr++)
            sE1[(rq * 16 + rr) * 132 + h] = acc[rr];
    }

    // ---- A-MMA persistent W1_hc fragments in registers ----
    // warp w: m-tile mt = w&7 (rows j0..j0+15), k-half khA = w>>3 (8 k-tiles)
    const int mt  = warp & 7;
    const int khA = warp >> 3;
    const int j0  = mt << 4;
    unsigned aw0[8], aw1[8], aw2[8], aw3[8];
    {
        const float* r0p = W1 + (j0 + g8) * 384 + (khA << 7) + tg * 2;
        const float* r1p = r0p + 8 * 384;
#pragma unroll
        for (int kt = 0; kt < 8; kt++) {
            int k = kt * 16;
            aw0[kt] = packh2(r0p[k],     r0p[k + 1]);
            aw1[kt] = packh2(r1p[k],     r1p[k + 1]);
            aw2[kt] = packh2(r0p[k + 8], r0p[k + 9]);
            aw3[kt] = packh2(r1p[k + 8], r1p[k + 9]);
        }
    }
    // shared B-operand row pointer (batch = g8; rows >=2 are zero)
    const __half* bbRow = sHch + ((g8 < 2) ? g8 : 2) * HCS + tg * 2;

    // ---- F ldmatrix bases (Whh rows 32w..32w+31) ----
    const unsigned whBase = (unsigned)__cvta_generic_to_shared(sWh);
    const unsigned sA0 = whBase +
        (((warp << 5) | (lane & 15)) * 136 + ((lane >> 4) << 3)) * 2;
    const unsigned sA1 = sA0 + 16 * 136 * 2;
    __syncthreads();

    for (int step = 0; step < TT; step++) {
        // ---- A: u[j,g] = W1_hc @ hc on tensor cores (A-frags in regs)
        {
            const __half* bA = bbRow + (khA << 7);
            float d0 = 0.f, d1 = 0.f, d2 = 0.f, d3 = 0.f;
            float f0 = 0.f, f1 = 0.f, f2 = 0.f, f3 = 0.f;
#pragma unroll
            for (int kt = 0; kt < 8; kt += 2) {
                unsigned b0 = *reinterpret_cast<const unsigned*>(bA + kt * 16);
                unsigned b1 = *reinterpret_cast<const unsigned*>(bA + kt * 16 + 8);
                MMA16816(d0, d1, d2, d3,
                         aw0[kt], aw1[kt], aw2[kt], aw3[kt], b0, b1);
                unsigned c0 = *reinterpret_cast<const unsigned*>(bA + kt * 16 + 16);
                unsigned c1 = *reinterpret_cast<const unsigned*>(bA + kt * 16 + 24);
                MMA16816(f0, f1, f2, f3,
                         aw0[kt + 1], aw1[kt + 1], aw2[kt + 1], aw3[kt + 1],
                         c0, c1);
            }
            if (tg == 0) {
                float* P = sup + (khA << 1) * 132;   // [khA][g][132]
                P[j0 + g8]             = d0 + f0;    // g0
                P[132 + j0 + g8]       = d1 + f1;    // g1
                P[j0 + g8 + 8]         = d2 + f2;
                P[132 + j0 + g8 + 8]   = d3 + f3;
            }
        }
        __syncthreads();

        // ---- B: 64 logits; warp covers 4 rows via 8-lane groups
        {
            int c8 = lane & 7, pr = lane >> 3;
            int p  = (warp << 2) | pr;
            int pg = p >> 5, pt = p & 31;
            const float4* e1r = reinterpret_cast<const float4*>(
                sE1 + (pg * 32 + pt) * 132);
            const float4* u0r = reinterpret_cast<const float4*>(sup + pg * 132);
            const float4* u1r = reinterpret_cast<const float4*>(sup + 264 + pg * 132);
            const float4* wr  = reinterpret_cast<const float4*>(sW2);
            float s = 0.f;
#pragma unroll
            for (int c = 0; c < 4; c++) {
                int idx = c * 8 + c8;
                float4 e = e1r[idx], ua = u0r[idx], ub = u1r[idx], w = wr[idx];
                s += fast_tanh(e.x + ua.x + ub.x) * w.x
                   + fast_tanh(e.y + ua.y + ub.y) * w.y
                   + fast_tanh(e.z + ua.z + ub.z) * w.z
                   + fast_tanh(e.w + ua.w + ub.w) * w.w;
            }
            s += __shfl_xor_sync(0xffffffffu, s, 1);
            s += __shfl_xor_sync(0xffffffffu, s, 2);
            s += __shfl_xor_sync(0xffffffffu, s, 4);
            if (c8 == 0) slogS[p] = s;
        }
        // ---- F: gates = Whh @ h on tensor cores (overlaps B, no barrier)
        {
            float d00 = 0.f, d01 = 0.f, d02 = 0.f, d03 = 0.f;
            float d10 = 0.f, d11 = 0.f, d12 = 0.f, d13 = 0.f;
#pragma unroll
            for (int kt = 0; kt < 8; kt++) {
                unsigned a0, a1, a2, a3, e0, e1, e2, e3;
                asm volatile(
                    "ldmatrix.sync.aligned.m8n8.x4.shared.b16 {%0,%1,%2,%3}, [%4];"
                    : "=r"(a0), "=r"(a1), "=r"(a2), "=r"(a3)
                    : "r"(sA0 + kt * 32));
                asm volatile(
                    "ldmatrix.sync.aligned.m8n8.x4.shared.b16 {%0,%1,%2,%3}, [%4];"
                    : "=r"(e0), "=r"(e1), "=r"(e2), "=r"(e3)
                    : "r"(sA1 + kt * 32));
                unsigned b0 = *reinterpret_cast<const unsigned*>(bbRow + kt * 16);
                unsigned b1 = *reinterpret_cast<const unsigned*>(bbRow + kt * 16 + 8);
                MMA16816(d00, d01, d02, d03, a0, a1, a2, a3, b0, b1);
                MMA16816(d10, d11, d12, d13, e0, e1, e2, e3, b0, b1);
            }
            if (tg == 0) {   // cols 0,1 = batches 0,1
                int r0 = (warp << 5) | g8;
                sgates[r0]            = d00;  sgates[512 + r0]      = d01;
                sgates[r0 + 8]        = d02;  sgates[512 + r0 + 8]  = d03;
                sgates[r0 + 16]       = d10;  sgates[512 + r0 + 16] = d11;
                sgates[r0 + 24]       = d12;  sgates[512 + r0 + 24] = d13;
            }
        }
        __syncthreads();

        // ---- C+D+E-partials (softmax in regs — logits bounded, no max pass)
        {
            int g  = warp >> 3;
            int wb = warp & 7;
            float l = slogS[g * 32 + lane];
            float e = __expf(l);          // |l| <= sum|W2| ~ 6 : safe
            float sum = e;
#pragma unroll
            for (int o = 16; o > 0; o >>= 1)
                sum += __shfl_xor_sync(0xffffffffu, sum, o);
            float a = e / sum;

            int jp = (wb << 3) | (lane & 7);
            int ts = lane >> 3;
            const ULL* e2 = reinterpret_cast<const ULL*>(sEnc) + g * 2112 + jp;
            ULL acc = 0;
#pragma unroll
            for (int i = 0; i < 8; i++) {
                int t = ts * 8 + i;
                ULL av = pack2(__shfl_sync(0xffffffffu, a, t));
                acc = fma2(av, e2[t * 66], acc);
            }
            float2 v = unpack2(acc);
            v.x += __shfl_xor_sync(0xffffffffu, v.x, 8);
            v.y += __shfl_xor_sync(0xffffffffu, v.y, 8);
            v.x += __shfl_xor_sync(0xffffffffu, v.x, 16);
            v.y += __shfl_xor_sync(0xffffffffu, v.y, 16);
            float px = 0.f;
            if (ts == 0) {
                reinterpret_cast<float2*>(sctxC)[g * 64 + jp] = v;
                px = v.x * sfc[2 * jp] + v.y * sfc[2 * jp + 1];
            }
            px += __shfl_xor_sync(0xffffffffu, px, 1);
            px += __shfl_xor_sync(0xffffffffu, px, 2);
            px += __shfl_xor_sync(0xffffffffu, px, 4);
            if (lane == 0) sEp[g * 8 + wb] = px;
        }
        __syncthreads();

        // ---- G: y_tilde combine + LSTM cell (fp32 master + fp16 hc shadow)
        if (tid < 256) {
            int j = tid & 127, g = tid >> 7;
            const float* ep = sEp + g * 8;
            float y = ep[0] + ep[1] + ep[2] + ep[3]
                    + ep[4] + ep[5] + ep[6] + ep[7]
                    + sy[g * 32 + step] * sfc[128] + sfc[129];
            float gv[4];
#pragma unroll
            for (int q = 0; q < 4; q++) {
                int r = q * 128 + j;
                gv[q] = sgates[g * 512 + r] + sbias[r] + y * sWih[r];
            }
            int hq = j >> 6, ho = j & 63;
            float* hb = sHp + g * HB;
            float c_old = hb[(2 + hq) * HQ + ho];
            float si = fast_sig(gv[0]);
            float sf = fast_sig(gv[1]);
            float so = fast_sig(gv[3]);
            float cn = sf * c_old + si * fast_tanh(gv[2]);
            float hn = so * fast_tanh(cn);
            hb[(2 + hq) * HQ + ho] = cn;
            hb[hq * HQ + ho]       = hn;
            __half* hr = sHch + g * HCS;
            hr[j]       = __float2half(hn);
            hr[128 + j] = __float2half(cn);
        }
        __syncthreads();
    }

    // ---- final: out[b] = [h, ctx] . fcfW + fcfb + y_history[b, 31]
    if (warp < 2) {
        int g = warp;
        float4 hv = reinterpret_cast<const float4*>(sHp + g * HB)
                        [(lane >> 4) * 17 + (lane & 15)];
        float4 f1 = reinterpret_cast<const float4*>(sfcf)[lane];
        float4 cv = reinterpret_cast<const float4*>(sctxC + g * 128)[lane];
        float4 f2 = reinterpret_cast<const float4*>(sfcf + 128)[lane];
        float s = hv.x * f1.x + hv.y * f1.y + hv.z * f1.z + hv.w * f1.w
                + cv.x * f2.x + cv.y * f2.y + cv.z * f2.z + cv.w * f2.w;
#pragma unroll
        for (int o = 16; o > 0; o >>= 1)
            s += __shfl_xor_sync(0xffffffffu, s, o);
        if (lane == 0)
            out[bp + g] = s + sfc[130] + sy[g * 32 + 31];
    }
}

// ---------------------------------------------------------------------------
extern "C" void kernel_launch(void* const* d_in, const int* in_sizes, int n_in,
                              void* d_out, int out_size)
{
    const float* enc  = (const float*)d_in[0];
    const float* yh   = (const float*)d_in[1];
    const float* W1   = (const float*)d_in[2];
    const float* b1   = (const float*)d_in[3];
    const float* W2   = (const float*)d_in[4];
    // d_in[5] = attn_b2 : constant shift, cancels in softmax
    const float* Wih  = (const float*)d_in[6];
    const float* Whh  = (const float*)d_in[7];
    const float* bih  = (const float*)d_in[8];
    const float* bhh  = (const float*)d_in[9];
    const float* fcW  = (const float*)d_in[10];
    const float* fcb  = (const float*)d_in[11];
    const float* fcfW = (const float*)d_in[12];
    const float* fcfb = (const float*)d_in[13];
    float* out = (float*)d_out;

    const size_t smem_floats = 34816 + 8448 + 8448 + 552 + 1056 + 1024
                             + 528 + 256 + 512 + 512 + 128 + 256 + 132
                             + 64 + 64 + 16;
    const size_t smem = smem_floats * sizeof(float);   // 227,248 B

    cudaFuncSetAttribute(decoder_kernel,
                         cudaFuncAttributeMaxDynamicSharedMemorySize, (int)smem);
    cudaFuncSetAttribute(decoder_kernel,
                         cudaFuncAttributePreferredSharedMemoryCarveout, 100);

    whh_prep<<<8, 128>>>(Whh);
    decoder_kernel<<<128, 512, smem>>>(enc, yh, W1, b1, W2, Wih, bih, bhh,
                                       fcW, fcb, fcfW, fcfb, out);
}

// round 12
// speedup vs baseline: 1.8462x; 1.2028x over previous
#include <cuda_runtime.h>
#include <cuda_fp16.h>

#define BB 256
#define TT 32

// Device-global scratch: Whh fp16 row-major padded [512][136] (272B rows)
__device__ __half g_WhhH[512 * 136];

__device__ __forceinline__ float fast_tanh(float x) {
    float y;
    asm("tanh.approx.f32 %0, %1;" : "=f"(y) : "f"(x));
    return y;
}
__device__ __forceinline__ float fast_sig(float x) {
    return 0.5f + 0.5f * fast_tanh(0.5f * x);
}
__device__ __forceinline__ unsigned packh2(float x, float y) {
    __half2 h = __floats2half2_rn(x, y);
    return *reinterpret_cast<unsigned*>(&h);
}

#define MMA16816(d0,d1,d2,d3,a0,a1,a2,a3,b0,b1)                              \
    asm volatile(                                                            \
        "mma.sync.aligned.m16n8k16.row.col.f32.f16.f16.f32 "                 \
        "{%0,%1,%2,%3}, {%4,%5,%6,%7}, {%8,%9}, {%0,%1,%2,%3};"              \
        : "+f"(d0), "+f"(d1), "+f"(d2), "+f"(d3)                             \
        : "r"(a0), "r"(a1), "r"(a2), "r"(a3), "r"(b0), "r"(b1))

// fp32 master hc layout: quarters of 64 floats at stride 68; batch stride 272.
#define HQ 68
#define HB 272
// fp16 hc shadow: rows = batch (8 rows, 2 real), 264 halves per row.
#define HCS 264

// ---------------------------------------------------------------------------
// Prep: Whh fp32 -> fp16 row-major padded [512][136]
// ---------------------------------------------------------------------------
__global__ void __launch_bounds__(128)
whh_prep(const float* __restrict__ Whh)   // [512,128]
{
    int base = blockIdx.x * 8704;
    for (int i = base + threadIdx.x; i < base + 8704; i += 128) {
        int r = i / 136, k = i % 136;
        g_WhhH[i] = __float2half((k < 128) ? Whh[r * 128 + k] : 0.f);
    }
}

// ---------------------------------------------------------------------------
// Main: 128 blocks x 512 threads, 2 batches/block. 3 barriers per step.
// A and F on tensor cores; per-step ctx eliminated via ef[t]=enc_t.fcW trick.
// ---------------------------------------------------------------------------
__global__ void __launch_bounds__(512, 1)
decoder_kernel(const float* __restrict__ enc,     // [B,32,128]
               const float* __restrict__ yhist,   // [B,32]
               const float* __restrict__ W1,      // [128,384] cols [h|c|enc]
               const float* __restrict__ b1,      // [128]
               const float* __restrict__ W2,      // [128]
               const float* __restrict__ Wih,     // [512]
               const float* __restrict__ bih,     // [512]
               const float* __restrict__ bhh,     // [512]
               const float* __restrict__ fcW,     // [129]
               const float* __restrict__ fcb,     // [1]
               const float* __restrict__ fcfW,    // [256]
               const float* __restrict__ fcfb,    // [1]
               float* __restrict__ out)           // [256]
{
    extern __shared__ float sm[];
    __half* sWh   = (__half*)sm;          // [512][136] fp16 = 34816 fl
    float*  sEnc  = sm + 34816;           // 8448 [64 rows][132]
    float*  sE1   = sEnc + 8448;          // 8448 [64 rows][132]
    float*  sHp   = sE1 + 8448;           // 552  fp32 master hc [g][q][68]
    __half* sHch  = (__half*)(sHp + 552); // [8][264] fp16 hc shadow = 1056 fl
    float*  sgates= sHp + 552 + 1056;     // 1024 [g][512]
    float*  sup   = sgates + 1024;        // 528  [kh][g][132] u partials
    float*  sctxC = sup + 528;            // 256  [g][128] final ctx only
    float*  sWih  = sctxC + 256;          // 512
    float*  sbias = sWih + 512;           // 512
    float*  sW2   = sbias + 512;          // 128
    float*  sfcf  = sW2 + 128;            // 256
    float*  sfc   = sfcf + 256;           // 132: fcW[0..129), [129]=fcb, [130]=fcfb
    float*  sy    = sfc + 132;            // 64  [g][32]
    float*  slogS = sy + 64;              // 64
    float*  sEf   = slogS + 64;           // 64  [g][32] enc_t . fcW
    float*  sAtt  = sEf + 64;             // 64  [g][32] last-step attn

    const int tid  = threadIdx.x;
    const int lane = tid & 31;
    const int warp = tid >> 5;
    const int bp   = blockIdx.x * 2;

    // MMA lane coordinates
    const int tg = lane & 3;     // quad id (k selector)
    const int g8 = lane >> 2;    // group id (row / col-n selector)

    // ---- load phase ----
    for (int i = tid; i < 8704; i += 512)
        reinterpret_cast<uint4*>(sWh)[i] =
            reinterpret_cast<const uint4*>(g_WhhH)[i];
    for (int i4 = tid; i4 < 2048; i4 += 512) {
        int r = i4 >> 5, c = i4 & 31;
        reinterpret_cast<float4*>(sEnc)[r * 33 + c] =
            reinterpret_cast<const float4*>(enc + (size_t)bp * 4096)[i4];
    }
    sWih[tid]  = Wih[tid];
    sbias[tid] = bih[tid] + bhh[tid];
    if (tid < 552) sHp[tid] = 0.f;
    for (int i = tid; i < 1056; i += 512)
        reinterpret_cast<float*>(sHch)[i] = 0.f;
    if (tid < 128) sW2[tid]  = W2[tid];
    if (tid < 256) sfcf[tid] = fcfW[tid];
    if (tid < 131)
        sfc[tid] = (tid < 129) ? fcW[tid] : (tid == 129) ? fcb[0] : fcfb[0];
    if (tid < 64) sy[tid] = yhist[(bp + (tid >> 5)) * 32 + (tid & 31)];
    __syncthreads();

    // ---- E1 = enc @ W1e^T + b1, in-CTA once ----
    {
        int h = tid & 127, rq = tid >> 7;
        float acc[16];
        float bb = b1[h];
#pragma unroll
        for (int rr = 0; rr < 16; rr++) acc[rr] = bb;
        const float4* wsrc = reinterpret_cast<const float4*>(W1 + h * 384 + 256);
#pragma unroll
        for (int ch = 0; ch < 4; ch++) {
            float4 w[8];
#pragma unroll
            for (int kk = 0; kk < 8; kk++) w[kk] = wsrc[ch * 8 + kk];
#pragma unroll
            for (int rr = 0; rr < 16; rr++) {
                const float4* ev = reinterpret_cast<const float4*>(
                    sEnc + (rq * 16 + rr) * 132) + ch * 8;
                float s = 0.f;
#pragma unroll
                for (int kk = 0; kk < 8; kk++) {
                    float4 e = ev[kk];
                    s += w[kk].x * e.x + w[kk].y * e.y
                       + w[kk].z * e.z + w[kk].w * e.w;
                }
                acc[rr] += s;
            }
        }
#pragma unroll
        for (int rr = 0; rr < 16; rr++)
            sE1[(rq * 16 + rr) * 132 + h] = acc[rr];
    }

    // ---- ef[p] = enc row p . fcW (y_tilde-without-ctx trick) ----
    {
        int c8 = lane & 7, pr = lane >> 3;
        int p  = (warp << 2) | pr;   // p = g*32 + t
        const float4* er = reinterpret_cast<const float4*>(sEnc + p * 132);
        const float4* fr = reinterpret_cast<const float4*>(sfc);
        float s = 0.f;
#pragma unroll
        for (int c = 0; c < 4; c++) {
            int idx = c * 8 + c8;
            float4 e = er[idx], f = fr[idx];
            s += e.x * f.x + e.y * f.y + e.z * f.z + e.w * f.w;
        }
        s += __shfl_xor_sync(0xffffffffu, s, 1);
        s += __shfl_xor_sync(0xffffffffu, s, 2);
        s += __shfl_xor_sync(0xffffffffu, s, 4);
        if (c8 == 0) sEf[p] = s;
    }

    // ---- A-MMA persistent W1_hc fragments in registers ----
    // warp w: m-tile mt = w&7 (rows j0..j0+15), k-half khA = w>>3 (8 k-tiles)
    const int mt  = warp & 7;
    const int khA = warp >> 3;
    const int j0  = mt << 4;
    unsigned aw0[8], aw1[8], aw2[8], aw3[8];
    {
        const float* r0p = W1 + (j0 + g8) * 384 + (khA << 7) + tg * 2;
        const float* r1p = r0p + 8 * 384;
#pragma unroll
        for (int kt = 0; kt < 8; kt++) {
            int k = kt * 16;
            aw0[kt] = packh2(r0p[k],     r0p[k + 1]);
            aw1[kt] = packh2(r1p[k],     r1p[k + 1]);
            aw2[kt] = packh2(r0p[k + 8], r0p[k + 9]);
            aw3[kt] = packh2(r1p[k + 8], r1p[k + 9]);
        }
    }
    // shared B-operand row pointer (batch = g8; rows >=2 are zero)
    const __half* bbRow = sHch + ((g8 < 2) ? g8 : 2) * HCS + tg * 2;

    // ---- F ldmatrix bases (Whh rows 32w..32w+31) ----
    const unsigned whBase = (unsigned)__cvta_generic_to_shared(sWh);
    const unsigned sA0 = whBase +
        (((warp << 5) | (lane & 15)) * 136 + ((lane >> 4) << 3)) * 2;
    const unsigned sA1 = sA0 + 16 * 136 * 2;
    __syncthreads();

    // per-thread constants for G' (valid for tid < 256)
    const float ef_reg = sEf[((tid >> 7) << 5) | lane];
    const float yco = sfc[128], ycb = sfc[129];

    for (int step = 0; step < TT; step++) {
        // ---- A: u[j,g] = W1_hc @ hc on tensor cores (A-frags in regs)
        {
            const __half* bA = bbRow + (khA << 7);
            float d0 = 0.f, d1 = 0.f, d2 = 0.f, d3 = 0.f;
            float f0 = 0.f, f1 = 0.f, f2 = 0.f, f3 = 0.f;
#pragma unroll
            for (int kt = 0; kt < 8; kt += 2) {
                unsigned b0 = *reinterpret_cast<const unsigned*>(bA + kt * 16);
                unsigned b1 = *reinterpret_cast<const unsigned*>(bA + kt * 16 + 8);
                MMA16816(d0, d1, d2, d3,
                         aw0[kt], aw1[kt], aw2[kt], aw3[kt], b0, b1);
                unsigned c0 = *reinterpret_cast<const unsigned*>(bA + kt * 16 + 16);
                unsigned c1 = *reinterpret_cast<const unsigned*>(bA + kt * 16 + 24);
                MMA16816(f0, f1, f2, f3,
                         aw0[kt + 1], aw1[kt + 1], aw2[kt + 1], aw3[kt + 1],
                         c0, c1);
            }
            if (tg == 0) {
                float* P = sup + (khA << 1) * 132;   // [khA][g][132]
                P[j0 + g8]             = d0 + f0;    // g0
                P[132 + j0 + g8]       = d1 + f1;    // g1
                P[j0 + g8 + 8]         = d2 + f2;
                P[132 + j0 + g8 + 8]   = d3 + f3;
            }
        }
        __syncthreads();

        // ---- B: 64 logits; warp covers 4 rows via 8-lane groups
        {
            int c8 = lane & 7, pr = lane >> 3;
            int p  = (warp << 2) | pr;
            int pg = p >> 5, pt = p & 31;
            const float4* e1r = reinterpret_cast<const float4*>(
                sE1 + (pg * 32 + pt) * 132);
            const float4* u0r = reinterpret_cast<const float4*>(sup + pg * 132);
            const float4* u1r = reinterpret_cast<const float4*>(sup + 264 + pg * 132);
            const float4* wr  = reinterpret_cast<const float4*>(sW2);
            float s = 0.f;
#pragma unroll
            for (int c = 0; c < 4; c++) {
                int idx = c * 8 + c8;
                float4 e = e1r[idx], ua = u0r[idx], ub = u1r[idx], w = wr[idx];
                s += fast_tanh(e.x + ua.x + ub.x) * w.x
                   + fast_tanh(e.y + ua.y + ub.y) * w.y
                   + fast_tanh(e.z + ua.z + ub.z) * w.z
                   + fast_tanh(e.w + ua.w + ub.w) * w.w;
            }
            s += __shfl_xor_sync(0xffffffffu, s, 1);
            s += __shfl_xor_sync(0xffffffffu, s, 2);
            s += __shfl_xor_sync(0xffffffffu, s, 4);
            if (c8 == 0) slogS[p] = s;
        }
        // ---- F: gates = Whh @ h on tensor cores (overlaps B, no barrier)
        {
            float d00 = 0.f, d01 = 0.f, d02 = 0.f, d03 = 0.f;
            float d10 = 0.f, d11 = 0.f, d12 = 0.f, d13 = 0.f;
#pragma unroll
            for (int kt = 0; kt < 8; kt++) {
                unsigned a0, a1, a2, a3, e0, e1, e2, e3;
                asm volatile(
                    "ldmatrix.sync.aligned.m8n8.x4.shared.b16 {%0,%1,%2,%3}, [%4];"
                    : "=r"(a0), "=r"(a1), "=r"(a2), "=r"(a3)
                    : "r"(sA0 + kt * 32));
                asm volatile(
                    "ldmatrix.sync.aligned.m8n8.x4.shared.b16 {%0,%1,%2,%3}, [%4];"
                    : "=r"(e0), "=r"(e1), "=r"(e2), "=r"(e3)
                    : "r"(sA1 + kt * 32));
                unsigned b0 = *reinterpret_cast<const unsigned*>(bbRow + kt * 16);
                unsigned b1 = *reinterpret_cast<const unsigned*>(bbRow + kt * 16 + 8);
                MMA16816(d00, d01, d02, d03, a0, a1, a2, a3, b0, b1);
                MMA16816(d10, d11, d12, d13, e0, e1, e2, e3, b0, b1);
            }
            if (tg == 0) {   // cols 0,1 = batches 0,1
                int r0 = (warp << 5) | g8;
                sgates[r0]            = d00;  sgates[512 + r0]      = d01;
                sgates[r0 + 8]        = d02;  sgates[512 + r0 + 8]  = d03;
                sgates[r0 + 16]       = d10;  sgates[512 + r0 + 16] = d11;
                sgates[r0 + 24]       = d12;  sgates[512 + r0 + 24] = d13;
            }
        }
        __syncthreads();

        // ---- G': in-warp softmax + y_tilde + LSTM cell (8 warps)
        if (tid < 256) {
            int j = tid & 127, g = tid >> 7;
            // softmax over t = lane (logits bounded: no max pass needed)
            float l = slogS[(g << 5) | lane];
            float e = __expf(l);
            float sum = e, wy = e * ef_reg;
#pragma unroll
            for (int o = 16; o > 0; o >>= 1) {
                sum += __shfl_xor_sync(0xffffffffu, sum, o);
                wy  += __shfl_xor_sync(0xffffffffu, wy, o);
            }
            float y = __fdividef(wy, sum) + sy[(g << 5) | step] * yco + ycb;
            float gv[4];
#pragma unroll
            for (int q = 0; q < 4; q++) {
                int r = q * 128 + j;
                gv[q] = sgates[g * 512 + r] + sbias[r] + y * sWih[r];
            }
            int hq = j >> 6, ho = j & 63;
            float* hb = sHp + g * HB;
            float c_old = hb[(2 + hq) * HQ + ho];
            float si = fast_sig(gv[0]);
            float sf = fast_sig(gv[1]);
            float so = fast_sig(gv[3]);
            float cn = sf * c_old + si * fast_tanh(gv[2]);
            float hn = so * fast_tanh(cn);
            hb[(2 + hq) * HQ + ho] = cn;
            hb[hq * HQ + ho]       = hn;
            __half* hr = sHch + g * HCS;
            hr[j]       = __float2half(hn);
            hr[128 + j] = __float2half(cn);
            // stash final-step attention for the output ctx
            if (step == TT - 1 && ((tid >> 5) & 3) == 0)
                sAtt[(g << 5) | lane] = __fdividef(e, sum);
        }
        __syncthreads();
    }

    // ---- final ctx[g][j] = sum_t attn_t * enc[t][j]  (8 warps, once)
    if (warp < 8) {
        int g = warp >> 2;
        int j = ((warp & 3) << 5) | lane;
        const float* eb = sEnc + g * 32 * 132 + j;
        const float* ab = sAtt + g * 32;
        float acc = 0.f;
#pragma unroll
        for (int t = 0; t < 32; t++)
            acc = fmaf(ab[t], eb[t * 132], acc);
        sctxC[g * 128 + j] = acc;
    }
    __syncthreads();

    // ---- final: out[b] = [h, ctx] . fcfW + fcfb + y_history[b, 31]
    if (warp < 2) {
        int g = warp;
        float4 hv = reinterpret_cast<const float4*>(sHp + g * HB)
                        [(lane >> 4) * 17 + (lane & 15)];
        float4 f1 = reinterpret_cast<const float4*>(sfcf)[lane];
        float4 cv = reinterpret_cast<const float4*>(sctxC + g * 128)[lane];
        float4 f2 = reinterpret_cast<const float4*>(sfcf + 128)[lane];
        float s = hv.x * f1.x + hv.y * f1.y + hv.z * f1.z + hv.w * f1.w
                + cv.x * f2.x + cv.y * f2.y + cv.z * f2.z + cv.w * f2.w;
#pragma unroll
        for (int o = 16; o > 0; o >>= 1)
            s += __shfl_xor_sync(0xffffffffu, s, o);
        if (lane == 0)
            out[bp + g] = s + sfc[130] + sy[(g << 5) | 31];
    }
}

// ---------------------------------------------------------------------------
extern "C" void kernel_launch(void* const* d_in, const int* in_sizes, int n_in,
                              void* d_out, int out_size)
{
    const float* enc  = (const float*)d_in[0];
    const float* yh   = (const float*)d_in[1];
    const float* W1   = (const float*)d_in[2];
    const float* b1   = (const float*)d_in[3];
    const float* W2   = (const float*)d_in[4];
    // d_in[5] = attn_b2 : constant shift, cancels in softmax
    const float* Wih  = (const float*)d_in[6];
    const float* Whh  = (const float*)d_in[7];
    const float* bih  = (const float*)d_in[8];
    const float* bhh  = (const float*)d_in[9];
    const float* fcW  = (const float*)d_in[10];
    const float* fcb  = (const float*)d_in[11];
    const float* fcfW = (const float*)d_in[12];
    const float* fcfb = (const float*)d_in[13];
    float* out = (float*)d_out;

    const size_t smem_floats = 34816 + 8448 + 8448 + 552 + 1056 + 1024
                             + 528 + 256 + 512 + 512 + 128 + 256 + 132
                             + 64 + 64 + 64 + 64;
    const size_t smem = smem_floats * sizeof(float);   // 227,696 B

    cudaFuncSetAttribute(decoder_kernel,
                         cudaFuncAttributeMaxDynamicSharedMemorySize, (int)smem);
    cudaFuncSetAttribute(decoder_kernel,
                         cudaFuncAttributePreferredSharedMemoryCarveout, 100);

    whh_prep<<<8, 128>>>(Whh);
    decoder_kernel<<<128, 512, smem>>>(enc, yh, W1, b1, W2, Wih, bih, bhh,
                                       fcW, fcb, fcfW, fcfb, out);
}